// round 1
// baseline (speedup 1.0000x reference)
#include <cuda_runtime.h>
#include <cstdint>
#include <cstddef>

// Problem dims (fixed by the dataset)
#define BN   1024      // B*N rows
#define DD   768       // audio feature dim
#define TT   512       // CLIP token dim
#define VV   49408     // vocab size

// ---------------- static device workspace (no runtime allocs) ----------------
__device__ float g_kw[BN * TT];                       // projected+normalized keywords
__device__ float g_inv[VV];                           // 1/max(||emb_v||, eps)
__device__ float g_invs[BN];                          // 1/softmax_sum per row
__device__ float g_logits[(size_t)BN * VV];           // logits -> unnormalized probs (202 MB)

// =============================================================================
// Generic NN SGEMM tile: C[M,N] += A[M,K] * B[K,N], 128x128 tile, BK=16,
// 256 threads, 8x8 register micro-tile. blockIdx.z splits K (kChunk each).
// EPI==0: C = acc + bias[n]   (plain store, used for projection)
// EPI==1: atomicAdd(C, acc * rowscale[m])  (split-K VQ GEMM epilogue)
// =============================================================================
template<int EPI>
__global__ __launch_bounds__(256, 2)
void gemm_nn_kernel(const float* __restrict__ A, const float* __restrict__ B,
                    const float* __restrict__ aux, float* __restrict__ C,
                    int M, int N, int K, int kChunk)
{
    __shared__ float As[16][132];   // transposed A tile As[k][m], padded
    __shared__ float Bs[16][132];   // direct B tile Bs[k][n], padded (132%4==0 keeps f4 align)

    const int tid = threadIdx.x;
    const int m0 = blockIdx.y * 128;
    const int n0 = blockIdx.x * 128;
    const int k_begin = blockIdx.z * kChunk;
    const int k_end   = k_begin + kChunk;

    const int tx = tid & 15;        // 16 col-threads
    const int ty = tid >> 4;        // 16 row-threads

    // A tile loader: 128 rows x 16 cols = 512 float4; 2 per thread
    const int a_row = tid >> 2;
    const int a_c4  = (tid & 3) * 4;
    // B tile loader: 16 rows x 128 cols = 512 float4; 2 per thread
    const int b_k   = tid >> 5;
    const int b_n4  = (tid & 31) * 4;

    float acc[8][8];
    #pragma unroll
    for (int i = 0; i < 8; i++)
        #pragma unroll
        for (int j = 0; j < 8; j++) acc[i][j] = 0.f;

    for (int k0 = k_begin; k0 < k_end; k0 += 16) {
        // ---- A tile (transposed store) ----
        float4 va0 = *(const float4*)&A[(size_t)(m0 + a_row)      * K + k0 + a_c4];
        float4 va1 = *(const float4*)&A[(size_t)(m0 + a_row + 64) * K + k0 + a_c4];
        As[a_c4 + 0][a_row] = va0.x;  As[a_c4 + 1][a_row] = va0.y;
        As[a_c4 + 2][a_row] = va0.z;  As[a_c4 + 3][a_row] = va0.w;
        As[a_c4 + 0][a_row + 64] = va1.x;  As[a_c4 + 1][a_row + 64] = va1.y;
        As[a_c4 + 2][a_row + 64] = va1.z;  As[a_c4 + 3][a_row + 64] = va1.w;
        // ---- B tile (direct store) ----
        float4 vb0 = *(const float4*)&B[(size_t)(k0 + b_k)     * N + n0 + b_n4];
        float4 vb1 = *(const float4*)&B[(size_t)(k0 + b_k + 8) * N + n0 + b_n4];
        *(float4*)&Bs[b_k][b_n4]     = vb0;
        *(float4*)&Bs[b_k + 8][b_n4] = vb1;
        __syncthreads();

        #pragma unroll
        for (int kk = 0; kk < 16; kk++) {
            float a[8], b[8];
            *(float4*)&a[0] = *(const float4*)&As[kk][ty * 8];
            *(float4*)&a[4] = *(const float4*)&As[kk][ty * 8 + 4];
            *(float4*)&b[0] = *(const float4*)&Bs[kk][tx * 8];
            *(float4*)&b[4] = *(const float4*)&Bs[kk][tx * 8 + 4];
            #pragma unroll
            for (int i = 0; i < 8; i++)
                #pragma unroll
                for (int j = 0; j < 8; j++)
                    acc[i][j] = fmaf(a[i], b[j], acc[i][j]);
        }
        __syncthreads();
    }

    if (EPI == 0) {
        // bias + store
        #pragma unroll
        for (int i = 0; i < 8; i++) {
            const int m = m0 + ty * 8 + i;
            #pragma unroll
            for (int j4 = 0; j4 < 2; j4++) {
                const int n = n0 + tx * 8 + j4 * 4;
                float4 r;
                r.x = acc[i][j4 * 4 + 0] + aux[n + 0];
                r.y = acc[i][j4 * 4 + 1] + aux[n + 1];
                r.z = acc[i][j4 * 4 + 2] + aux[n + 2];
                r.w = acc[i][j4 * 4 + 3] + aux[n + 3];
                *(float4*)&C[(size_t)m * N + n] = r;
            }
        }
    } else {
        // split-K: atomic accumulate with per-row softmax 1/sum
        #pragma unroll
        for (int i = 0; i < 8; i++) {
            const int m = m0 + ty * 8 + i;
            const float s = aux[m];
            #pragma unroll
            for (int j = 0; j < 8; j++) {
                atomicAdd(&C[(size_t)m * N + n0 + tx * 8 + j], acc[i][j] * s);
            }
        }
    }
}

// =============================================================================
// NT SGEMM: logits[1024, 49408] = (kw_n[1024,512] . emb[v,512]) * inv_norm[v] * 10
// Both operands K-major (row-major with K contiguous).
// =============================================================================
__global__ __launch_bounds__(256, 2)
void gemm_nt_logits(const float* __restrict__ A, const float* __restrict__ B,
                    const float* __restrict__ invn, float* __restrict__ C)
{
    __shared__ float As[16][132];
    __shared__ float Bs[16][132];

    const int tid = threadIdx.x;
    const int m0 = blockIdx.y * 128;
    const int n0 = blockIdx.x * 128;

    const int tx = tid & 15;
    const int ty = tid >> 4;

    const int l_row = tid >> 2;
    const int l_c4  = (tid & 3) * 4;

    float acc[8][8];
    #pragma unroll
    for (int i = 0; i < 8; i++)
        #pragma unroll
        for (int j = 0; j < 8; j++) acc[i][j] = 0.f;

    for (int k0 = 0; k0 < TT; k0 += 16) {
        float4 va0 = *(const float4*)&A[(size_t)(m0 + l_row)      * TT + k0 + l_c4];
        float4 va1 = *(const float4*)&A[(size_t)(m0 + l_row + 64) * TT + k0 + l_c4];
        As[l_c4 + 0][l_row] = va0.x;  As[l_c4 + 1][l_row] = va0.y;
        As[l_c4 + 2][l_row] = va0.z;  As[l_c4 + 3][l_row] = va0.w;
        As[l_c4 + 0][l_row + 64] = va1.x;  As[l_c4 + 1][l_row + 64] = va1.y;
        As[l_c4 + 2][l_row + 64] = va1.z;  As[l_c4 + 3][l_row + 64] = va1.w;

        float4 vb0 = *(const float4*)&B[(size_t)(n0 + l_row)      * TT + k0 + l_c4];
        float4 vb1 = *(const float4*)&B[(size_t)(n0 + l_row + 64) * TT + k0 + l_c4];
        Bs[l_c4 + 0][l_row] = vb0.x;  Bs[l_c4 + 1][l_row] = vb0.y;
        Bs[l_c4 + 2][l_row] = vb0.z;  Bs[l_c4 + 3][l_row] = vb0.w;
        Bs[l_c4 + 0][l_row + 64] = vb1.x;  Bs[l_c4 + 1][l_row + 64] = vb1.y;
        Bs[l_c4 + 2][l_row + 64] = vb1.z;  Bs[l_c4 + 3][l_row + 64] = vb1.w;
        __syncthreads();

        #pragma unroll
        for (int kk = 0; kk < 16; kk++) {
            float a[8], b[8];
            *(float4*)&a[0] = *(const float4*)&As[kk][ty * 8];
            *(float4*)&a[4] = *(const float4*)&As[kk][ty * 8 + 4];
            *(float4*)&b[0] = *(const float4*)&Bs[kk][tx * 8];
            *(float4*)&b[4] = *(const float4*)&Bs[kk][tx * 8 + 4];
            #pragma unroll
            for (int i = 0; i < 8; i++)
                #pragma unroll
                for (int j = 0; j < 8; j++)
                    acc[i][j] = fmaf(a[i], b[j], acc[i][j]);
        }
        __syncthreads();
    }

    // epilogue: cosine scale (1/||emb_v||) and 1/TEMP
    float sc[8];
    #pragma unroll
    for (int j = 0; j < 8; j++) sc[j] = invn[n0 + tx * 8 + j] * 10.0f;

    #pragma unroll
    for (int i = 0; i < 8; i++) {
        const int m = m0 + ty * 8 + i;
        #pragma unroll
        for (int j4 = 0; j4 < 2; j4++) {
            const int n = n0 + tx * 8 + j4 * 4;
            float4 r;
            r.x = acc[i][j4 * 4 + 0] * sc[j4 * 4 + 0];
            r.y = acc[i][j4 * 4 + 1] * sc[j4 * 4 + 1];
            r.z = acc[i][j4 * 4 + 2] * sc[j4 * 4 + 2];
            r.w = acc[i][j4 * 4 + 3] * sc[j4 * 4 + 3];
            *(float4*)&C[(size_t)m * VV + n] = r;
        }
    }
}

// =============================================================================
// Row L2-normalize in place (one warp per 512-float row), eps = 1e-8 (max).
// =============================================================================
__global__ void kw_norm_kernel(float* __restrict__ kw)
{
    const int w    = (blockIdx.x * blockDim.x + threadIdx.x) >> 5;
    const int lane = threadIdx.x & 31;
    if (w >= BN) return;
    float4* row = (float4*)(kw + (size_t)w * TT);
    float4 v[4];
    float ss = 0.f;
    #pragma unroll
    for (int q = 0; q < 4; q++) {
        v[q] = row[lane + 32 * q];
        ss += v[q].x * v[q].x + v[q].y * v[q].y + v[q].z * v[q].z + v[q].w * v[q].w;
    }
    #pragma unroll
    for (int o = 16; o > 0; o >>= 1) ss += __shfl_xor_sync(0xffffffffu, ss, o);
    const float inv = 1.f / fmaxf(sqrtf(ss), 1e-8f);
    #pragma unroll
    for (int q = 0; q < 4; q++) {
        v[q].x *= inv; v[q].y *= inv; v[q].z *= inv; v[q].w *= inv;
        row[lane + 32 * q] = v[q];
    }
}

// one warp per vocab row: inv_norm only
__global__ void emb_norm_kernel(const float* __restrict__ emb, float* __restrict__ inv)
{
    const int w    = (blockIdx.x * blockDim.x + threadIdx.x) >> 5;
    const int lane = threadIdx.x & 31;
    if (w >= VV) return;
    const float4* row = (const float4*)(emb + (size_t)w * TT);
    float ss = 0.f;
    #pragma unroll
    for (int q = 0; q < 4; q++) {
        float4 v = row[lane + 32 * q];
        ss += v.x * v.x + v.y * v.y + v.z * v.z + v.w * v.w;
    }
    #pragma unroll
    for (int o = 16; o > 0; o >>= 1) ss += __shfl_xor_sync(0xffffffffu, ss, o);
    if (lane == 0) inv[w] = 1.f / fmaxf(sqrtf(ss), 1e-8f);
}

// =============================================================================
// Softmax (unnormalized): x <- exp(x - rowmax); invs[row] = 1/sum.
// Normalization folded into VQ-GEMM epilogue (linear).
// =============================================================================
__global__ __launch_bounds__(256)
void softmax_kernel(float* __restrict__ logits, float* __restrict__ invs)
{
    const int row = blockIdx.x;
    float* x = logits + (size_t)row * VV;
    __shared__ float red[256];
    const int tid = threadIdx.x;

    // pass 1: row max
    float m = -1e30f;
    for (int k = tid; k < VV; k += 256) m = fmaxf(m, x[k]);
    red[tid] = m;
    __syncthreads();
    #pragma unroll
    for (int s = 128; s > 0; s >>= 1) {
        if (tid < s) red[tid] = fmaxf(red[tid], red[tid + s]);
        __syncthreads();
    }
    m = red[0];
    __syncthreads();

    // pass 2: exp + sum, store unnormalized probs
    float sum = 0.f;
    for (int k = tid; k < VV; k += 256) {
        const float e = __expf(x[k] - m);
        x[k] = e;
        sum += e;
    }
    red[tid] = sum;
    __syncthreads();
    #pragma unroll
    for (int s = 128; s > 0; s >>= 1) {
        if (tid < s) red[tid] += red[tid + s];
        __syncthreads();
    }
    if (tid == 0) invs[row] = 1.f / red[0];
}

// =============================================================================
// Launch
// =============================================================================
extern "C" void kernel_launch(void* const* d_in, const int* in_sizes, int n_in,
                              void* d_out, int out_size)
{
    const float* audio = (const float*)d_in[0];   // [128,8,768] -> [1024,768]
    const float* W     = (const float*)d_in[1];   // [768,512]
    const float* bias  = (const float*)d_in[2];   // [512]
    const float* emb   = (const float*)d_in[3];   // [49408,512]
    float* out = (float*)d_out;                   // [1024,512]

    float *kw, *inv, *invs, *logits;
    cudaGetSymbolAddress((void**)&kw,     g_kw);
    cudaGetSymbolAddress((void**)&inv,    g_inv);
    cudaGetSymbolAddress((void**)&invs,   g_invs);
    cudaGetSymbolAddress((void**)&logits, g_logits);

    // 1. projection: kw = audio @ W + b
    gemm_nn_kernel<0><<<dim3(TT / 128, BN / 128, 1), 256>>>(
        audio, W, bias, kw, BN, TT, DD, DD);

    // 2. normalize kw rows in place
    kw_norm_kernel<<<BN / 8, 256>>>(kw);

    // 3. embedding inverse norms
    emb_norm_kernel<<<VV / 8, 256>>>(emb, inv);

    // 4. logits = (kw_n . emb^T) * inv_norm * (1/TEMP)
    gemm_nt_logits<<<dim3(VV / 128, BN / 128), 256>>>(kw, emb, inv, logits);

    // 5. softmax (unnormalized) + 1/sum
    softmax_kernel<<<BN, 256>>>(logits, invs);

    // 6. zero output, then split-K VQ GEMM with scaled atomic accumulation
    cudaMemsetAsync(out, 0, (size_t)out_size * sizeof(float), 0);
    gemm_nn_kernel<1><<<dim3(TT / 128, BN / 128, 16), 256>>>(
        logits, emb, invs, out, BN, TT, VV, VV / 16);
}

// round 3
// speedup vs baseline: 1.9480x; 1.9480x over previous
#include <cuda_runtime.h>
#include <cuda_bf16.h>
#include <cstdint>
#include <cstddef>

#define BN 1024
#define DD 768
#define TT 512
#define VV 49408

// ------------------------- static device workspace --------------------------
__device__ float g_kw[BN * TT];            // projected keywords fp32
__device__ float g_inv[VV];                // 1/max(||emb_v||, eps)
__device__ float g_rowsum[BN];             // softmax denominators
__device__ __nv_bfloat16 g_kw_h[BN * TT],  g_kw_l[BN * TT];            // normalized kw
__device__ __nv_bfloat16 g_emb_h[(size_t)VV * TT], g_emb_l[(size_t)VV * TT];   // NORMALIZED emb [v][t]
__device__ __nv_bfloat16 g_embT_h[(size_t)TT * VV], g_embT_l[(size_t)TT * VV]; // raw emb^T [t][v]
__device__ __nv_bfloat16 g_probs_h[(size_t)BN * VV], g_probs_l[(size_t)BN * VV];

// ------------------------------ helpers -------------------------------------
__device__ __forceinline__ uint32_t smem_u32(const void* p) {
    uint32_t a;
    asm("{ .reg .u64 t; cvta.to.shared.u64 t, %1; cvt.u32.u64 %0, t; }"
        : "=r"(a) : "l"(p));
    return a;
}
__device__ __forceinline__ void cp16(uint32_t s, const void* g) {
    asm volatile("cp.async.cg.shared.global [%0], [%1], 16;" :: "r"(s), "l"(g));
}
__device__ __forceinline__ void ldsm4(uint32_t* r, uint32_t addr) {
    asm volatile("ldmatrix.sync.aligned.m8n8.x4.shared.b16 {%0,%1,%2,%3}, [%4];"
        : "=r"(r[0]), "=r"(r[1]), "=r"(r[2]), "=r"(r[3]) : "r"(addr));
}
__device__ __forceinline__ void mma16816(float* c, const uint32_t* a, const uint32_t* b) {
    asm volatile("mma.sync.aligned.m16n8k16.row.col.f32.bf16.bf16.f32 "
        "{%0,%1,%2,%3}, {%4,%5,%6,%7}, {%8,%9}, {%0,%1,%2,%3};"
        : "+f"(c[0]), "+f"(c[1]), "+f"(c[2]), "+f"(c[3])
        : "r"(a[0]), "r"(a[1]), "r"(a[2]), "r"(a[3]), "r"(b[0]), "r"(b[1]));
}
__device__ __forceinline__ void split_bf16(float x, __nv_bfloat16& h, __nv_bfloat16& l) {
    h = __float2bfloat16(x);
    l = __float2bfloat16(x - __bfloat162float(h));
}
__device__ __forceinline__ uint32_t pack2(__nv_bfloat16 a, __nv_bfloat16 b) {
    return (uint32_t)__bfloat16_as_ushort(a) | ((uint32_t)__bfloat16_as_ushort(b) << 16);
}

// smem layout per stage: Ah | Al | Bh | Bl, each 128 rows x 144 bytes
#define ROWB   144
#define PLANE  (128 * ROWB)      // 18432
#define STAGE  (4 * PLANE)       // 73728
#define SMEMSZ (2 * STAGE)       // 147456

__device__ __forceinline__ void issue_stage(
    uint32_t st, const __nv_bfloat16* Ah, const __nv_bfloat16* Al,
    const __nv_bfloat16* Bh, const __nv_bfloat16* Bl,
    size_t lda, size_t ldb, int m0, int n0, int kc, int tid)
{
    const size_t ka = (size_t)kc * 64;
    #pragma unroll
    for (int p = 0; p < 4; p++) {
        const int idx = tid + p * 256;
        const int row = idx >> 3, ch = idx & 7;
        const uint32_t so = (uint32_t)(row * ROWB + ch * 16);
        const size_t ea = (size_t)(m0 + row) * lda + ka + ch * 8;
        const size_t eb = (size_t)(n0 + row) * ldb + ka + ch * 8;
        cp16(st + so,             Ah + ea);
        cp16(st + PLANE + so,     Al + ea);
        cp16(st + 2 * PLANE + so, Bh + eb);
        cp16(st + 3 * PLANE + so, Bl + eb);
    }
}

// =============================================================================
// bf16x3 warp-MMA GEMM, CTA tile 128x128, BK=64, 256 thr, warp tile 64x32.
// EPI==0: logits -> exp epilogue -> packed probs planes + rowsum atomics
// EPI==1: VQ GEMM split-K -> scaled fp32 atomicAdd into out
// =============================================================================
template<int EPI>
__global__ __launch_bounds__(256, 1) void mma_gemm(float* __restrict__ outf)
{
    extern __shared__ char smem[];
    const uint32_t sbase = smem_u32(smem);
    const int tid = threadIdx.x;
    const int lane = tid & 31, wid = tid >> 5;
    const int warpM = wid & 1, warpN = wid >> 1;

    const __nv_bfloat16 *Ah, *Al, *Bh, *Bl;
    size_t lda, ldb;
    int m0, n0, c0, c1;
    if (EPI == 0) {
        Ah = g_kw_h; Al = g_kw_l; Bh = g_emb_h; Bl = g_emb_l;
        lda = TT; ldb = TT;
        m0 = blockIdx.x * 128; n0 = blockIdx.y * 128;
        c0 = 0; c1 = TT / 64;
    } else {
        Ah = g_probs_h; Al = g_probs_l; Bh = g_embT_h; Bl = g_embT_l;
        lda = VV; ldb = VV;
        n0 = blockIdx.x * 128; m0 = blockIdx.y * 128;
        const long tot = VV / 64;
        c0 = (int)((tot * blockIdx.z) / gridDim.z);
        c1 = (int)((tot * (blockIdx.z + 1)) / gridDim.z);
    }
    const int nch = c1 - c0;

    float acc[4][4][4];
    #pragma unroll
    for (int i = 0; i < 4; i++)
        #pragma unroll
        for (int j = 0; j < 4; j++)
            #pragma unroll
            for (int k = 0; k < 4; k++) acc[i][j][k] = 0.f;

    // prologue: 2 stages in flight (nch >= 2 always)
    issue_stage(sbase,         Ah, Al, Bh, Bl, lda, ldb, m0, n0, c0,     tid);
    asm volatile("cp.async.commit_group;" ::: "memory");
    issue_stage(sbase + STAGE, Ah, Al, Bh, Bl, lda, ldb, m0, n0, c0 + 1, tid);
    asm volatile("cp.async.commit_group;" ::: "memory");

    for (int c = 0; c < nch; c++) {
        asm volatile("cp.async.wait_group 1;" ::: "memory");
        __syncthreads();
        const uint32_t st = sbase + (uint32_t)(c & 1) * STAGE;
        const uint32_t sa = st + (uint32_t)((warpM * 64 + (lane & 15)) * ROWB + ((lane >> 4) << 4));
        const uint32_t sb = st + 2 * PLANE
                          + (uint32_t)((warpN * 32 + (lane & 15)) * ROWB + ((lane >> 4) << 4));
        #pragma unroll
        for (int ks = 0; ks < 4; ks++) {
            const uint32_t ko = ks * 32;
            uint32_t ah[4][4], alr[4][4], bh[2][4], blr[2][4];
            #pragma unroll
            for (int mf = 0; mf < 4; mf++) {
                ldsm4(ah[mf],  sa +         mf * (16 * ROWB) + ko);
                ldsm4(alr[mf], sa + PLANE + mf * (16 * ROWB) + ko);
            }
            #pragma unroll
            for (int g = 0; g < 2; g++) {
                ldsm4(bh[g],  sb +         g * (16 * ROWB) + ko);
                ldsm4(blr[g], sb + PLANE + g * (16 * ROWB) + ko);
            }
            #pragma unroll
            for (int mf = 0; mf < 4; mf++)
                #pragma unroll
                for (int nf = 0; nf < 4; nf++) {
                    uint32_t bhf[2] = { bh[nf >> 1][nf & 1],  bh[nf >> 1][2 + (nf & 1)] };
                    uint32_t blf[2] = { blr[nf >> 1][nf & 1], blr[nf >> 1][2 + (nf & 1)] };
                    mma16816(acc[mf][nf], ah[mf],  bhf);   // Ah*Bh
                    mma16816(acc[mf][nf], ah[mf],  blf);   // Ah*Bl
                    mma16816(acc[mf][nf], alr[mf], bhf);   // Al*Bh
                }
        }
        __syncthreads();
        if (c + 2 < nch)
            issue_stage(sbase + (uint32_t)(c & 1) * STAGE,
                        Ah, Al, Bh, Bl, lda, ldb, m0, n0, c0 + c + 2, tid);
        asm volatile("cp.async.commit_group;" ::: "memory");
    }

    if (EPI == 0) {
        #pragma unroll
        for (int mf = 0; mf < 4; mf++) {
            const int r0 = m0 + warpM * 64 + mf * 16 + (lane >> 2);
            float rs0 = 0.f, rs1 = 0.f;
            #pragma unroll
            for (int nf = 0; nf < 4; nf++) {
                const int cb = n0 + warpN * 32 + nf * 8 + (lane & 3) * 2;
                const float e0 = __expf(acc[mf][nf][0] * 10.f - 10.f);
                const float e1 = __expf(acc[mf][nf][1] * 10.f - 10.f);
                const float e2 = __expf(acc[mf][nf][2] * 10.f - 10.f);
                const float e3 = __expf(acc[mf][nf][3] * 10.f - 10.f);
                rs0 += e0 + e1;  rs1 += e2 + e3;
                __nv_bfloat16 h0, l0, h1, l1;
                split_bf16(e0, h0, l0); split_bf16(e1, h1, l1);
                *(uint32_t*)&g_probs_h[(size_t)r0 * VV + cb] = pack2(h0, h1);
                *(uint32_t*)&g_probs_l[(size_t)r0 * VV + cb] = pack2(l0, l1);
                split_bf16(e2, h0, l0); split_bf16(e3, h1, l1);
                *(uint32_t*)&g_probs_h[(size_t)(r0 + 8) * VV + cb] = pack2(h0, h1);
                *(uint32_t*)&g_probs_l[(size_t)(r0 + 8) * VV + cb] = pack2(l0, l1);
            }
            rs0 += __shfl_xor_sync(0xffffffffu, rs0, 1);
            rs0 += __shfl_xor_sync(0xffffffffu, rs0, 2);
            rs1 += __shfl_xor_sync(0xffffffffu, rs1, 1);
            rs1 += __shfl_xor_sync(0xffffffffu, rs1, 2);
            if ((lane & 3) == 0) {
                atomicAdd(&g_rowsum[r0],     rs0);
                atomicAdd(&g_rowsum[r0 + 8], rs1);
            }
        }
    } else {
        #pragma unroll
        for (int mf = 0; mf < 4; mf++) {
            const int r0 = m0 + warpM * 64 + mf * 16 + (lane >> 2);
            const float s0 = 1.f / g_rowsum[r0];
            const float s1 = 1.f / g_rowsum[r0 + 8];
            #pragma unroll
            for (int nf = 0; nf < 4; nf++) {
                const int cb = n0 + warpN * 32 + nf * 8 + (lane & 3) * 2;
                atomicAdd(&outf[(size_t)r0 * TT + cb],           acc[mf][nf][0] * s0);
                atomicAdd(&outf[(size_t)r0 * TT + cb + 1],       acc[mf][nf][1] * s0);
                atomicAdd(&outf[(size_t)(r0 + 8) * TT + cb],     acc[mf][nf][2] * s1);
                atomicAdd(&outf[(size_t)(r0 + 8) * TT + cb + 1], acc[mf][nf][3] * s1);
            }
        }
    }
}

// =============================================================================
// fp32 SIMT projection GEMM (0.8 GF): kw = audio @ W + b
// =============================================================================
__global__ __launch_bounds__(256, 2)
void proj_gemm(const float* __restrict__ A, const float* __restrict__ B,
               const float* __restrict__ bias, float* __restrict__ C)
{
    __shared__ float As[16][132];
    __shared__ float Bs[16][132];
    const int tid = threadIdx.x;
    const int m0 = blockIdx.y * 128, n0 = blockIdx.x * 128;
    const int tx = tid & 15, ty = tid >> 4;
    const int a_row = tid >> 2, a_c4 = (tid & 3) * 4;
    const int b_k = tid >> 5, b_n4 = (tid & 31) * 4;

    float acc[8][8];
    #pragma unroll
    for (int i = 0; i < 8; i++)
        #pragma unroll
        for (int j = 0; j < 8; j++) acc[i][j] = 0.f;

    for (int k0 = 0; k0 < DD; k0 += 16) {
        float4 va0 = *(const float4*)&A[(size_t)(m0 + a_row)      * DD + k0 + a_c4];
        float4 va1 = *(const float4*)&A[(size_t)(m0 + a_row + 64) * DD + k0 + a_c4];
        As[a_c4 + 0][a_row] = va0.x;  As[a_c4 + 1][a_row] = va0.y;
        As[a_c4 + 2][a_row] = va0.z;  As[a_c4 + 3][a_row] = va0.w;
        As[a_c4 + 0][a_row + 64] = va1.x;  As[a_c4 + 1][a_row + 64] = va1.y;
        As[a_c4 + 2][a_row + 64] = va1.z;  As[a_c4 + 3][a_row + 64] = va1.w;
        *(float4*)&Bs[b_k][b_n4]     = *(const float4*)&B[(size_t)(k0 + b_k)     * TT + n0 + b_n4];
        *(float4*)&Bs[b_k + 8][b_n4] = *(const float4*)&B[(size_t)(k0 + b_k + 8) * TT + n0 + b_n4];
        __syncthreads();
        #pragma unroll
        for (int kk = 0; kk < 16; kk++) {
            float a[8], b[8];
            *(float4*)&a[0] = *(const float4*)&As[kk][ty * 8];
            *(float4*)&a[4] = *(const float4*)&As[kk][ty * 8 + 4];
            *(float4*)&b[0] = *(const float4*)&Bs[kk][tx * 8];
            *(float4*)&b[4] = *(const float4*)&Bs[kk][tx * 8 + 4];
            #pragma unroll
            for (int i = 0; i < 8; i++)
                #pragma unroll
                for (int j = 0; j < 8; j++)
                    acc[i][j] = fmaf(a[i], b[j], acc[i][j]);
        }
        __syncthreads();
    }
    #pragma unroll
    for (int i = 0; i < 8; i++) {
        const int m = m0 + ty * 8 + i;
        #pragma unroll
        for (int j4 = 0; j4 < 2; j4++) {
            const int n = n0 + tx * 8 + j4 * 4;
            float4 r;
            r.x = acc[i][j4 * 4 + 0] + bias[n + 0];
            r.y = acc[i][j4 * 4 + 1] + bias[n + 1];
            r.z = acc[i][j4 * 4 + 2] + bias[n + 2];
            r.w = acc[i][j4 * 4 + 3] + bias[n + 3];
            *(float4*)&C[(size_t)m * TT + n] = r;
        }
    }
}

// normalize kw rows -> hi/lo planes
__global__ void kw_norm_pack()
{
    const int w    = (blockIdx.x * blockDim.x + threadIdx.x) >> 5;
    const int lane = threadIdx.x & 31;
    if (w >= BN) return;
    const float4* row = (const float4*)(g_kw + (size_t)w * TT);
    float4 v[4];
    float ss = 0.f;
    #pragma unroll
    for (int q = 0; q < 4; q++) {
        v[q] = row[lane + 32 * q];
        ss += v[q].x * v[q].x + v[q].y * v[q].y + v[q].z * v[q].z + v[q].w * v[q].w;
    }
    #pragma unroll
    for (int o = 16; o > 0; o >>= 1) ss += __shfl_xor_sync(0xffffffffu, ss, o);
    const float inv = 1.f / fmaxf(sqrtf(ss), 1e-8f);
    #pragma unroll
    for (int q = 0; q < 4; q++) {
        const int e0 = (lane + 32 * q) * 4;
        const float xs[4] = { v[q].x * inv, v[q].y * inv, v[q].z * inv, v[q].w * inv };
        #pragma unroll
        for (int t = 0; t < 4; t++) {
            __nv_bfloat16 h, l;
            split_bf16(xs[t], h, l);
            g_kw_h[(size_t)w * TT + e0 + t] = h;
            g_kw_l[(size_t)w * TT + e0 + t] = l;
        }
    }
}

// per-vocab-row inverse norms
__global__ void emb_norm(const float* __restrict__ emb)
{
    const int w    = (blockIdx.x * blockDim.x + threadIdx.x) >> 5;
    const int lane = threadIdx.x & 31;
    if (w >= VV) return;
    const float4* row = (const float4*)(emb + (size_t)w * TT);
    float ss = 0.f;
    #pragma unroll
    for (int q = 0; q < 4; q++) {
        float4 v = row[lane + 32 * q];
        ss += v.x * v.x + v.y * v.y + v.z * v.z + v.w * v.w;
    }
    #pragma unroll
    for (int o = 16; o > 0; o >>= 1) ss += __shfl_xor_sync(0xffffffffu, ss, o);
    if (lane == 0) g_inv[w] = 1.f / fmaxf(sqrtf(ss), 1e-8f);
}

// pack emb: normalized K-major planes [v][t] AND raw transposed planes [t][v]
__global__ void trans_pack(const float* __restrict__ emb)
{
    __shared__ float tile[32][33];
    const int v0 = blockIdx.x * 32, t0 = blockIdx.y * 32;
    const int tx = threadIdx.x, ty = threadIdx.y;   // 32 x 8
    #pragma unroll
    for (int i = 0; i < 4; i++) {
        const int v = v0 + ty + i * 8;
        const float x = emb[(size_t)v * TT + t0 + tx];
        tile[ty + i * 8][tx] = x;
        const float xn = x * g_inv[v];
        __nv_bfloat16 h, l;
        split_bf16(xn, h, l);
        g_emb_h[(size_t)v * TT + t0 + tx] = h;
        g_emb_l[(size_t)v * TT + t0 + tx] = l;
    }
    __syncthreads();
    #pragma unroll
    for (int i = 0; i < 4; i++) {
        const int t = t0 + ty + i * 8;
        const float x = tile[tx][ty + i * 8];
        __nv_bfloat16 h, l;
        split_bf16(x, h, l);
        g_embT_h[(size_t)t * VV + v0 + tx] = h;
        g_embT_l[(size_t)t * VV + v0 + tx] = l;
    }
}

// =============================================================================
extern "C" void kernel_launch(void* const* d_in, const int* in_sizes, int n_in,
                              void* d_out, int out_size)
{
    const float* audio = (const float*)d_in[0];
    const float* W     = (const float*)d_in[1];
    const float* bias  = (const float*)d_in[2];
    const float* emb   = (const float*)d_in[3];
    float* out = (float*)d_out;

    cudaFuncSetAttribute(mma_gemm<0>, cudaFuncAttributeMaxDynamicSharedMemorySize, SMEMSZ);
    cudaFuncSetAttribute(mma_gemm<1>, cudaFuncAttributeMaxDynamicSharedMemorySize, SMEMSZ);

    float *kw, *rowsum;
    cudaGetSymbolAddress((void**)&kw,     g_kw);
    cudaGetSymbolAddress((void**)&rowsum, g_rowsum);

    proj_gemm<<<dim3(TT / 128, BN / 128), 256>>>(audio, W, bias, kw);
    kw_norm_pack<<<BN / 8, 256>>>();
    emb_norm<<<VV / 8, 256>>>(emb);
    trans_pack<<<dim3(VV / 32, TT / 32), dim3(32, 8)>>>(emb);
    cudaMemsetAsync(rowsum, 0, BN * sizeof(float), 0);

    // GEMM1: logits + exp epilogue. x = m-tiles (8, fastest -> B-tile L2 reuse), y = n-tiles (386)
    mma_gemm<0><<<dim3(BN / 128, VV / 128), 256, SMEMSZ>>>(nullptr);

    cudaMemsetAsync(out, 0, (size_t)out_size * sizeof(float), 0);
    // GEMM2: x = n-tiles (4), y = m-tiles (8), z = split-K (16)
    mma_gemm<1><<<dim3(TT / 128, BN / 128, 16), 256, SMEMSZ>>>(out);
}

// round 4
// speedup vs baseline: 4.7132x; 2.4195x over previous
#include <cuda_runtime.h>
#include <cuda_fp16.h>
#include <cstdint>
#include <cstddef>

#define BN 1024
#define DD 768
#define TT 512
#define VV 49408

// ------------------------- static device workspace --------------------------
__device__ float g_kw[BN * TT];            // projected keywords fp32
__device__ float g_inv[VV];                // 1/max(||emb_v||, eps)
__device__ float g_rowsum[BN];             // softmax denominators (scaled)
__device__ __half g_kwH[BN * TT];                  // normalized kw, fp16
__device__ __half g_embH[(size_t)VV * TT];         // NORMALIZED emb [v][t], fp16
__device__ __half g_embT[(size_t)TT * VV];         // raw emb^T [t][v], fp16
__device__ __half g_probs[(size_t)BN * VV];        // scaled unnormalized probs, fp16

// ------------------------------ helpers -------------------------------------
__device__ __forceinline__ uint32_t smem_u32(const void* p) {
    uint32_t a;
    asm("{ .reg .u64 t; cvta.to.shared.u64 t, %1; cvt.u32.u64 %0, t; }"
        : "=r"(a) : "l"(p));
    return a;
}
__device__ __forceinline__ void cp16(uint32_t s, const void* g) {
    asm volatile("cp.async.cg.shared.global [%0], [%1], 16;" :: "r"(s), "l"(g));
}
__device__ __forceinline__ void ldsm4(uint32_t* r, uint32_t addr) {
    asm volatile("ldmatrix.sync.aligned.m8n8.x4.shared.b16 {%0,%1,%2,%3}, [%4];"
        : "=r"(r[0]), "=r"(r[1]), "=r"(r[2]), "=r"(r[3]) : "r"(addr));
}
__device__ __forceinline__ void mma16816(float* c, const uint32_t* a, const uint32_t* b) {
    asm volatile("mma.sync.aligned.m16n8k16.row.col.f32.f16.f16.f32 "
        "{%0,%1,%2,%3}, {%4,%5,%6,%7}, {%8,%9}, {%0,%1,%2,%3};"
        : "+f"(c[0]), "+f"(c[1]), "+f"(c[2]), "+f"(c[3])
        : "r"(a[0]), "r"(a[1]), "r"(a[2]), "r"(a[3]), "r"(b[0]), "r"(b[1]));
}
__device__ __forceinline__ uint32_t pack2h(__half a, __half b) {
    return (uint32_t)__half_as_ushort(a) | ((uint32_t)__half_as_ushort(b) << 16);
}

// smem layout per stage: A | B, each 128 rows x 144 bytes (64 fp16 + 16B pad)
#define ROWB   144
#define PLANE  (128 * ROWB)      // 18432
#define STAGE  (2 * PLANE)       // 36864
#define SMEMSZ (2 * STAGE)       // 73728  -> 2 CTAs/SM

__device__ __forceinline__ void issue_stage(
    uint32_t st, const __half* A, const __half* B,
    size_t lda, size_t ldb, int m0, int n0, int kc, int tid)
{
    const size_t ka = (size_t)kc * 64;
    #pragma unroll
    for (int p = 0; p < 4; p++) {
        const int idx = tid + p * 256;
        const int row = idx >> 3, ch = idx & 7;
        const uint32_t so = (uint32_t)(row * ROWB + ch * 16);
        cp16(st + so,         A + (size_t)(m0 + row) * lda + ka + ch * 8);
        cp16(st + PLANE + so, B + (size_t)(n0 + row) * ldb + ka + ch * 8);
    }
}

// =============================================================================
// fp16 warp-MMA GEMM, CTA tile 128x128, BK=64, 256 thr, warp tile 64x32.
// EPI==0: logits -> exp epilogue -> scaled fp16 probs + rowsum atomics
// EPI==1: VQ GEMM split-K -> (1/rowsum)-scaled fp32 atomicAdd into out
// =============================================================================
template<int EPI>
__global__ __launch_bounds__(256, 2) void mma_gemm(float* __restrict__ outf)
{
    extern __shared__ char smem[];
    const uint32_t sbase = smem_u32(smem);
    const int tid = threadIdx.x;
    const int lane = tid & 31, wid = tid >> 5;
    const int warpM = wid & 1, warpN = wid >> 1;

    const __half *A, *B;
    size_t lda, ldb;
    int m0, n0, c0, c1;
    if (EPI == 0) {
        A = g_kwH; B = g_embH; lda = TT; ldb = TT;
        m0 = blockIdx.x * 128; n0 = blockIdx.y * 128;
        c0 = 0; c1 = TT / 64;
    } else {
        A = g_probs; B = g_embT; lda = VV; ldb = VV;
        n0 = blockIdx.x * 128; m0 = blockIdx.y * 128;
        const long tot = VV / 64;
        c0 = (int)((tot * blockIdx.z) / gridDim.z);
        c1 = (int)((tot * (blockIdx.z + 1)) / gridDim.z);
    }
    const int nch = c1 - c0;

    float acc[4][4][4];
    #pragma unroll
    for (int i = 0; i < 4; i++)
        #pragma unroll
        for (int j = 0; j < 4; j++)
            #pragma unroll
            for (int k = 0; k < 4; k++) acc[i][j][k] = 0.f;

    issue_stage(sbase,         A, B, lda, ldb, m0, n0, c0,     tid);
    asm volatile("cp.async.commit_group;" ::: "memory");
    issue_stage(sbase + STAGE, A, B, lda, ldb, m0, n0, c0 + 1, tid);
    asm volatile("cp.async.commit_group;" ::: "memory");

    for (int c = 0; c < nch; c++) {
        asm volatile("cp.async.wait_group 1;" ::: "memory");
        __syncthreads();
        const uint32_t st = sbase + (uint32_t)(c & 1) * STAGE;
        const uint32_t sa = st + (uint32_t)((warpM * 64 + (lane & 15)) * ROWB + ((lane >> 4) << 4));
        const uint32_t sb = st + PLANE
                          + (uint32_t)((warpN * 32 + (lane & 15)) * ROWB + ((lane >> 4) << 4));
        #pragma unroll
        for (int ks = 0; ks < 4; ks++) {
            const uint32_t ko = ks * 32;
            uint32_t a[4][4], b[2][4];
            #pragma unroll
            for (int mf = 0; mf < 4; mf++)
                ldsm4(a[mf], sa + mf * (16 * ROWB) + ko);
            #pragma unroll
            for (int g = 0; g < 2; g++)
                ldsm4(b[g], sb + g * (16 * ROWB) + ko);
            #pragma unroll
            for (int mf = 0; mf < 4; mf++)
                #pragma unroll
                for (int nf = 0; nf < 4; nf++) {
                    uint32_t bf[2] = { b[nf >> 1][nf & 1], b[nf >> 1][2 + (nf & 1)] };
                    mma16816(acc[mf][nf], a[mf], bf);
                }
        }
        __syncthreads();
        if (c + 2 < nch)
            issue_stage(sbase + (uint32_t)(c & 1) * STAGE,
                        A, B, lda, ldb, m0, n0, c0 + c + 2, tid);
        asm volatile("cp.async.commit_group;" ::: "memory");
    }

    if (EPI == 0) {
        #pragma unroll
        for (int mf = 0; mf < 4; mf++) {
            const int r0 = m0 + warpM * 64 + mf * 16 + (lane >> 2);
            float rs0 = 0.f, rs1 = 0.f;
            #pragma unroll
            for (int nf = 0; nf < 4; nf++) {
                const int cb = n0 + warpN * 32 + nf * 8 + (lane & 3) * 2;
                // p = exp(10*cos - 10) * 4096  (scale cancels in normalization)
                const float e0 = __expf(acc[mf][nf][0] * 10.f - 10.f) * 4096.f;
                const float e1 = __expf(acc[mf][nf][1] * 10.f - 10.f) * 4096.f;
                const float e2 = __expf(acc[mf][nf][2] * 10.f - 10.f) * 4096.f;
                const float e3 = __expf(acc[mf][nf][3] * 10.f - 10.f) * 4096.f;
                rs0 += e0 + e1;  rs1 += e2 + e3;
                *(uint32_t*)&g_probs[(size_t)r0 * VV + cb] =
                    pack2h(__float2half_rn(e0), __float2half_rn(e1));
                *(uint32_t*)&g_probs[(size_t)(r0 + 8) * VV + cb] =
                    pack2h(__float2half_rn(e2), __float2half_rn(e3));
            }
            rs0 += __shfl_xor_sync(0xffffffffu, rs0, 1);
            rs0 += __shfl_xor_sync(0xffffffffu, rs0, 2);
            rs1 += __shfl_xor_sync(0xffffffffu, rs1, 1);
            rs1 += __shfl_xor_sync(0xffffffffu, rs1, 2);
            if ((lane & 3) == 0) {
                atomicAdd(&g_rowsum[r0],     rs0);
                atomicAdd(&g_rowsum[r0 + 8], rs1);
            }
        }
    } else {
        #pragma unroll
        for (int mf = 0; mf < 4; mf++) {
            const int r0 = m0 + warpM * 64 + mf * 16 + (lane >> 2);
            const float s0 = 1.f / g_rowsum[r0];
            const float s1 = 1.f / g_rowsum[r0 + 8];
            #pragma unroll
            for (int nf = 0; nf < 4; nf++) {
                const int cb = n0 + warpN * 32 + nf * 8 + (lane & 3) * 2;
                atomicAdd(&outf[(size_t)r0 * TT + cb],           acc[mf][nf][0] * s0);
                atomicAdd(&outf[(size_t)r0 * TT + cb + 1],       acc[mf][nf][1] * s0);
                atomicAdd(&outf[(size_t)(r0 + 8) * TT + cb],     acc[mf][nf][2] * s1);
                atomicAdd(&outf[(size_t)(r0 + 8) * TT + cb + 1], acc[mf][nf][3] * s1);
            }
        }
    }
}

// =============================================================================
// fp32 SIMT projection GEMM (0.8 GF): kw = audio @ W + b
// =============================================================================
__global__ __launch_bounds__(256, 2)
void proj_gemm(const float* __restrict__ A, const float* __restrict__ B,
               const float* __restrict__ bias, float* __restrict__ C)
{
    __shared__ float As[16][132];
    __shared__ float Bs[16][132];
    const int tid = threadIdx.x;
    const int m0 = blockIdx.y * 128, n0 = blockIdx.x * 128;
    const int tx = tid & 15, ty = tid >> 4;
    const int a_row = tid >> 2, a_c4 = (tid & 3) * 4;
    const int b_k = tid >> 5, b_n4 = (tid & 31) * 4;

    float acc[8][8];
    #pragma unroll
    for (int i = 0; i < 8; i++)
        #pragma unroll
        for (int j = 0; j < 8; j++) acc[i][j] = 0.f;

    for (int k0 = 0; k0 < DD; k0 += 16) {
        float4 va0 = *(const float4*)&A[(size_t)(m0 + a_row)      * DD + k0 + a_c4];
        float4 va1 = *(const float4*)&A[(size_t)(m0 + a_row + 64) * DD + k0 + a_c4];
        As[a_c4 + 0][a_row] = va0.x;  As[a_c4 + 1][a_row] = va0.y;
        As[a_c4 + 2][a_row] = va0.z;  As[a_c4 + 3][a_row] = va0.w;
        As[a_c4 + 0][a_row + 64] = va1.x;  As[a_c4 + 1][a_row + 64] = va1.y;
        As[a_c4 + 2][a_row + 64] = va1.z;  As[a_c4 + 3][a_row + 64] = va1.w;
        *(float4*)&Bs[b_k][b_n4]     = *(const float4*)&B[(size_t)(k0 + b_k)     * TT + n0 + b_n4];
        *(float4*)&Bs[b_k + 8][b_n4] = *(const float4*)&B[(size_t)(k0 + b_k + 8) * TT + n0 + b_n4];
        __syncthreads();
        #pragma unroll
        for (int kk = 0; kk < 16; kk++) {
            float a[8], b[8];
            *(float4*)&a[0] = *(const float4*)&As[kk][ty * 8];
            *(float4*)&a[4] = *(const float4*)&As[kk][ty * 8 + 4];
            *(float4*)&b[0] = *(const float4*)&Bs[kk][tx * 8];
            *(float4*)&b[4] = *(const float4*)&Bs[kk][tx * 8 + 4];
            #pragma unroll
            for (int i = 0; i < 8; i++)
                #pragma unroll
                for (int j = 0; j < 8; j++)
                    acc[i][j] = fmaf(a[i], b[j], acc[i][j]);
        }
        __syncthreads();
    }
    #pragma unroll
    for (int i = 0; i < 8; i++) {
        const int m = m0 + ty * 8 + i;
        #pragma unroll
        for (int j4 = 0; j4 < 2; j4++) {
            const int n = n0 + tx * 8 + j4 * 4;
            float4 r;
            r.x = acc[i][j4 * 4 + 0] + bias[n + 0];
            r.y = acc[i][j4 * 4 + 1] + bias[n + 1];
            r.z = acc[i][j4 * 4 + 2] + bias[n + 2];
            r.w = acc[i][j4 * 4 + 3] + bias[n + 3];
            *(float4*)&C[(size_t)m * TT + n] = r;
        }
    }
}

// normalize kw rows -> fp16
__global__ void kw_norm_pack()
{
    const int w    = (blockIdx.x * blockDim.x + threadIdx.x) >> 5;
    const int lane = threadIdx.x & 31;
    if (w >= BN) return;
    const float4* row = (const float4*)(g_kw + (size_t)w * TT);
    float4 v[4];
    float ss = 0.f;
    #pragma unroll
    for (int q = 0; q < 4; q++) {
        v[q] = row[lane + 32 * q];
        ss += v[q].x * v[q].x + v[q].y * v[q].y + v[q].z * v[q].z + v[q].w * v[q].w;
    }
    #pragma unroll
    for (int o = 16; o > 0; o >>= 1) ss += __shfl_xor_sync(0xffffffffu, ss, o);
    const float inv = 1.f / fmaxf(sqrtf(ss), 1e-8f);
    #pragma unroll
    for (int q = 0; q < 4; q++) {
        const int e0 = (lane + 32 * q) * 4;
        *(uint32_t*)&g_kwH[(size_t)w * TT + e0] =
            pack2h(__float2half_rn(v[q].x * inv), __float2half_rn(v[q].y * inv));
        *(uint32_t*)&g_kwH[(size_t)w * TT + e0 + 2] =
            pack2h(__float2half_rn(v[q].z * inv), __float2half_rn(v[q].w * inv));
    }
}

// per-vocab-row inverse norms
__global__ void emb_norm(const float* __restrict__ emb)
{
    const int w    = (blockIdx.x * blockDim.x + threadIdx.x) >> 5;
    const int lane = threadIdx.x & 31;
    if (w >= VV) return;
    const float4* row = (const float4*)(emb + (size_t)w * TT);
    float ss = 0.f;
    #pragma unroll
    for (int q = 0; q < 4; q++) {
        float4 v = row[lane + 32 * q];
        ss += v.x * v.x + v.y * v.y + v.z * v.z + v.w * v.w;
    }
    #pragma unroll
    for (int o = 16; o > 0; o >>= 1) ss += __shfl_xor_sync(0xffffffffu, ss, o);
    if (lane == 0) g_inv[w] = 1.f / fmaxf(sqrtf(ss), 1e-8f);
}

// pack emb: normalized K-major fp16 [v][t] AND raw transposed fp16 [t][v]
__global__ void trans_pack(const float* __restrict__ emb)
{
    __shared__ float tile[32][33];
    const int v0 = blockIdx.x * 32, t0 = blockIdx.y * 32;
    const int tx = threadIdx.x, ty = threadIdx.y;   // 32 x 8
    #pragma unroll
    for (int i = 0; i < 4; i++) {
        const int v = v0 + ty + i * 8;
        const float x = emb[(size_t)v * TT + t0 + tx];
        tile[ty + i * 8][tx] = x;
        g_embH[(size_t)v * TT + t0 + tx] = __float2half_rn(x * g_inv[v]);
    }
    __syncthreads();
    #pragma unroll
    for (int i = 0; i < 4; i++) {
        const int t = t0 + ty + i * 8;
        g_embT[(size_t)t * VV + v0 + tx] = __float2half_rn(tile[tx][ty + i * 8]);
    }
}

// =============================================================================
extern "C" void kernel_launch(void* const* d_in, const int* in_sizes, int n_in,
                              void* d_out, int out_size)
{
    const float* audio = (const float*)d_in[0];
    const float* W     = (const float*)d_in[1];
    const float* bias  = (const float*)d_in[2];
    const float* emb   = (const float*)d_in[3];
    float* out = (float*)d_out;

    cudaFuncSetAttribute(mma_gemm<0>, cudaFuncAttributeMaxDynamicSharedMemorySize, SMEMSZ);
    cudaFuncSetAttribute(mma_gemm<1>, cudaFuncAttributeMaxDynamicSharedMemorySize, SMEMSZ);

    float *kw, *rowsum;
    cudaGetSymbolAddress((void**)&kw,     g_kw);
    cudaGetSymbolAddress((void**)&rowsum, g_rowsum);

    proj_gemm<<<dim3(TT / 128, BN / 128), 256>>>(audio, W, bias, kw);
    kw_norm_pack<<<BN / 8, 256>>>();
    emb_norm<<<VV / 8, 256>>>(emb);
    trans_pack<<<dim3(VV / 32, TT / 32), dim3(32, 8)>>>(emb);
    cudaMemsetAsync(rowsum, 0, BN * sizeof(float), 0);

    // GEMM1: logits + exp epilogue. x = m-tiles (8, fastest -> B-tile L2 reuse)
    mma_gemm<0><<<dim3(BN / 128, VV / 128), 256, SMEMSZ>>>(nullptr);

    cudaMemsetAsync(out, 0, (size_t)out_size * sizeof(float), 0);
    // GEMM2: x = n-tiles (4), y = m-tiles (8), z = split-K (9) -> 288 CTAs ~ 1 wave
    mma_gemm<1><<<dim3(TT / 128, BN / 128, 9), 256, SMEMSZ>>>(out);
}

// round 5
// speedup vs baseline: 5.7061x; 1.2107x over previous
#include <cuda_runtime.h>
#include <cuda_fp16.h>
#include <cstdint>
#include <cstddef>

#define BN 1024
#define DD 768
#define TT 512
#define VV 49408

// ------------------------- static device workspace --------------------------
__device__ float g_kw[BN * TT];            // projected keywords fp32 (split-K accum)
__device__ float g_rowsum[BN];             // softmax denominators (scaled)
__device__ __half g_kwH[BN * TT];                  // normalized kw, fp16
__device__ __half g_embH[(size_t)VV * TT];         // NORMALIZED emb [v][t], fp16
__device__ __half g_embR[(size_t)VV * TT];         // RAW emb [v][t], fp16
__device__ __half g_probs[(size_t)BN * VV];        // scaled unnormalized probs, fp16

// ------------------------------ helpers -------------------------------------
__device__ __forceinline__ uint32_t smem_u32(const void* p) {
    uint32_t a;
    asm("{ .reg .u64 t; cvta.to.shared.u64 t, %1; cvt.u32.u64 %0, t; }"
        : "=r"(a) : "l"(p));
    return a;
}
__device__ __forceinline__ void cp16(uint32_t s, const void* g) {
    asm volatile("cp.async.cg.shared.global [%0], [%1], 16;" :: "r"(s), "l"(g));
}
__device__ __forceinline__ void ldsm4(uint32_t* r, uint32_t addr) {
    asm volatile("ldmatrix.sync.aligned.m8n8.x4.shared.b16 {%0,%1,%2,%3}, [%4];"
        : "=r"(r[0]), "=r"(r[1]), "=r"(r[2]), "=r"(r[3]) : "r"(addr));
}
__device__ __forceinline__ void ldsm4t(uint32_t* r, uint32_t addr) {
    asm volatile("ldmatrix.sync.aligned.m8n8.x4.trans.shared.b16 {%0,%1,%2,%3}, [%4];"
        : "=r"(r[0]), "=r"(r[1]), "=r"(r[2]), "=r"(r[3]) : "r"(addr));
}
__device__ __forceinline__ void mma16816(float* c, const uint32_t* a, const uint32_t* b) {
    asm volatile("mma.sync.aligned.m16n8k16.row.col.f32.f16.f16.f32 "
        "{%0,%1,%2,%3}, {%4,%5,%6,%7}, {%8,%9}, {%0,%1,%2,%3};"
        : "+f"(c[0]), "+f"(c[1]), "+f"(c[2]), "+f"(c[3])
        : "r"(a[0]), "r"(a[1]), "r"(a[2]), "r"(a[3]), "r"(b[0]), "r"(b[1]));
}
__device__ __forceinline__ uint32_t pack2h(__half a, __half b) {
    return (uint32_t)__half_as_ushort(a) | ((uint32_t)__half_as_ushort(b) << 16);
}

// smem: A plane 128x144B; B plane: EPI0 128x144B, EPI1 64x272B (both <= 18432)
#define ROWA   144
#define ROWBT  272
#define PLANE  18432
#define STAGE  (2 * PLANE)       // 36864
#define SMEMSZ (2 * STAGE)       // 73728 -> 2 CTAs/SM

template<int EPI>
__device__ __forceinline__ void issue_stage(
    uint32_t st, const __half* __restrict__ A, const __half* __restrict__ B,
    size_t lda, int m0, int n0, int kc, int tid)
{
    const size_t ka = (size_t)kc * 64;
    #pragma unroll
    for (int p = 0; p < 4; p++) {
        const int idx = tid + p * 256;
        const int row = idx >> 3, ch = idx & 7;
        cp16(st + (uint32_t)(row * ROWA + ch * 16),
             A + (size_t)(m0 + row) * lda + ka + ch * 8);
        if (EPI == 0) {
            // B = embH [v][t], rows are n (=v), k along t
            cp16(st + PLANE + (uint32_t)(row * ROWA + ch * 16),
                 B + (size_t)(n0 + row) * TT + ka + ch * 8);
        } else {
            // B = embR [v][t], rows are k (=v), n along t: 64 rows x 256B
            const int rb = idx >> 4, cb = idx & 15;
            cp16(st + PLANE + (uint32_t)(rb * ROWBT + cb * 16),
                 B + (ka + rb) * TT + n0 + cb * 8);
        }
    }
}

// =============================================================================
// fp16 warp-MMA GEMM, CTA tile 128x128, BK=64, 256 thr, warp tile 64x32.
// EPI==0: logits -> exp epilogue -> scaled fp16 probs + rowsum atomics
// EPI==1: VQ GEMM split-K (B via ldmatrix.trans on K-major emb) -> atomicAdd out
// =============================================================================
template<int EPI>
__global__ __launch_bounds__(256, 2) void mma_gemm(float* __restrict__ outf)
{
    extern __shared__ char smem[];
    const uint32_t sbase = smem_u32(smem);
    const int tid = threadIdx.x;
    const int lane = tid & 31, wid = tid >> 5;
    const int warpM = wid & 1, warpN = wid >> 1;

    const __half *A, *B;
    size_t lda;
    int m0, n0, c0, c1;
    if (EPI == 0) {
        A = g_kwH; B = g_embH; lda = TT;
        m0 = blockIdx.x * 128; n0 = blockIdx.y * 128;
        c0 = 0; c1 = TT / 64;
    } else {
        A = g_probs; B = g_embR; lda = VV;
        n0 = blockIdx.x * 128; m0 = blockIdx.y * 128;
        const long tot = VV / 64;
        c0 = (int)((tot * blockIdx.z) / gridDim.z);
        c1 = (int)((tot * (blockIdx.z + 1)) / gridDim.z);
    }
    const int nch = c1 - c0;

    float acc[4][4][4];
    #pragma unroll
    for (int i = 0; i < 4; i++)
        #pragma unroll
        for (int j = 0; j < 4; j++)
            #pragma unroll
            for (int k = 0; k < 4; k++) acc[i][j][k] = 0.f;

    issue_stage<EPI>(sbase,         A, B, lda, m0, n0, c0,     tid);
    asm volatile("cp.async.commit_group;" ::: "memory");
    issue_stage<EPI>(sbase + STAGE, A, B, lda, m0, n0, c0 + 1, tid);
    asm volatile("cp.async.commit_group;" ::: "memory");

    for (int c = 0; c < nch; c++) {
        asm volatile("cp.async.wait_group 1;" ::: "memory");
        __syncthreads();
        const uint32_t st = sbase + (uint32_t)(c & 1) * STAGE;
        const uint32_t sa = st + (uint32_t)((warpM * 64 + (lane & 15)) * ROWA + ((lane >> 4) << 4));
        #pragma unroll
        for (int ks = 0; ks < 4; ks++) {
            const uint32_t ko = ks * 32;
            uint32_t a[4][4], b[2][4];
            #pragma unroll
            for (int mf = 0; mf < 4; mf++)
                ldsm4(a[mf], sa + mf * (16 * ROWA) + ko);
            if (EPI == 0) {
                const uint32_t sb = st + PLANE
                    + (uint32_t)((warpN * 32 + (lane & 15)) * ROWA + ((lane >> 4) << 4));
                #pragma unroll
                for (int g = 0; g < 2; g++)
                    ldsm4(b[g], sb + g * (16 * ROWA) + ko);
            } else {
                // trans load: rows = k, cols = n (halves)
                const uint32_t sbb = st + PLANE
                    + (uint32_t)((ks * 16 + (lane & 7) + ((lane >> 4) << 3)) * ROWBT
                                 + (warpN * 32 + ((lane >> 3) & 1) * 8) * 2);
                #pragma unroll
                for (int g = 0; g < 2; g++)
                    ldsm4t(b[g], sbb + g * 32);   // +16 halves of n
            }
            #pragma unroll
            for (int mf = 0; mf < 4; mf++)
                #pragma unroll
                for (int nf = 0; nf < 4; nf++) {
                    uint32_t bf[2] = { b[nf >> 1][nf & 1], b[nf >> 1][2 + (nf & 1)] };
                    mma16816(acc[mf][nf], a[mf], bf);
                }
        }
        __syncthreads();
        if (c + 2 < nch)
            issue_stage<EPI>(sbase + (uint32_t)(c & 1) * STAGE,
                             A, B, lda, m0, n0, c0 + c + 2, tid);
        asm volatile("cp.async.commit_group;" ::: "memory");
    }

    if (EPI == 0) {
        #pragma unroll
        for (int mf = 0; mf < 4; mf++) {
            const int r0 = m0 + warpM * 64 + mf * 16 + (lane >> 2);
            float rs0 = 0.f, rs1 = 0.f;
            #pragma unroll
            for (int nf = 0; nf < 4; nf++) {
                const int cb = n0 + warpN * 32 + nf * 8 + (lane & 3) * 2;
                // p = exp(10*cos - 10) * 4096  (scale cancels in normalization)
                const float e0 = __expf(acc[mf][nf][0] * 10.f - 10.f) * 4096.f;
                const float e1 = __expf(acc[mf][nf][1] * 10.f - 10.f) * 4096.f;
                const float e2 = __expf(acc[mf][nf][2] * 10.f - 10.f) * 4096.f;
                const float e3 = __expf(acc[mf][nf][3] * 10.f - 10.f) * 4096.f;
                rs0 += e0 + e1;  rs1 += e2 + e3;
                *(uint32_t*)&g_probs[(size_t)r0 * VV + cb] =
                    pack2h(__float2half_rn(e0), __float2half_rn(e1));
                *(uint32_t*)&g_probs[(size_t)(r0 + 8) * VV + cb] =
                    pack2h(__float2half_rn(e2), __float2half_rn(e3));
            }
            rs0 += __shfl_xor_sync(0xffffffffu, rs0, 1);
            rs0 += __shfl_xor_sync(0xffffffffu, rs0, 2);
            rs1 += __shfl_xor_sync(0xffffffffu, rs1, 1);
            rs1 += __shfl_xor_sync(0xffffffffu, rs1, 2);
            if ((lane & 3) == 0) {
                atomicAdd(&g_rowsum[r0],     rs0);
                atomicAdd(&g_rowsum[r0 + 8], rs1);
            }
        }
    } else {
        #pragma unroll
        for (int mf = 0; mf < 4; mf++) {
            const int r0 = m0 + warpM * 64 + mf * 16 + (lane >> 2);
            const float s0 = 1.f / g_rowsum[r0];
            const float s1 = 1.f / g_rowsum[r0 + 8];
            #pragma unroll
            for (int nf = 0; nf < 4; nf++) {
                const int cb = n0 + warpN * 32 + nf * 8 + (lane & 3) * 2;
                atomicAdd(&outf[(size_t)r0 * TT + cb],           acc[mf][nf][0] * s0);
                atomicAdd(&outf[(size_t)r0 * TT + cb + 1],       acc[mf][nf][1] * s0);
                atomicAdd(&outf[(size_t)(r0 + 8) * TT + cb],     acc[mf][nf][2] * s1);
                atomicAdd(&outf[(size_t)(r0 + 8) * TT + cb + 1], acc[mf][nf][3] * s1);
            }
        }
    }
}

// =============================================================================
// fp32 SIMT projection GEMM, split-K z=4 (128 CTAs): kw += audio @ W
// (bias is applied in kw_norm_pack)
// =============================================================================
__global__ __launch_bounds__(256, 2)
void proj_gemm(const float* __restrict__ A, const float* __restrict__ B,
               float* __restrict__ C)
{
    __shared__ float As[16][132];
    __shared__ float Bs[16][132];
    const int tid = threadIdx.x;
    const int m0 = blockIdx.y * 128, n0 = blockIdx.x * 128;
    const int kb = blockIdx.z * (DD / 4), ke = kb + DD / 4;
    const int tx = tid & 15, ty = tid >> 4;
    const int a_row = tid >> 2, a_c4 = (tid & 3) * 4;
    const int b_k = tid >> 5, b_n4 = (tid & 31) * 4;

    float acc[8][8];
    #pragma unroll
    for (int i = 0; i < 8; i++)
        #pragma unroll
        for (int j = 0; j < 8; j++) acc[i][j] = 0.f;

    for (int k0 = kb; k0 < ke; k0 += 16) {
        float4 va0 = *(const float4*)&A[(size_t)(m0 + a_row)      * DD + k0 + a_c4];
        float4 va1 = *(const float4*)&A[(size_t)(m0 + a_row + 64) * DD + k0 + a_c4];
        As[a_c4 + 0][a_row] = va0.x;  As[a_c4 + 1][a_row] = va0.y;
        As[a_c4 + 2][a_row] = va0.z;  As[a_c4 + 3][a_row] = va0.w;
        As[a_c4 + 0][a_row + 64] = va1.x;  As[a_c4 + 1][a_row + 64] = va1.y;
        As[a_c4 + 2][a_row + 64] = va1.z;  As[a_c4 + 3][a_row + 64] = va1.w;
        *(float4*)&Bs[b_k][b_n4]     = *(const float4*)&B[(size_t)(k0 + b_k)     * TT + n0 + b_n4];
        *(float4*)&Bs[b_k + 8][b_n4] = *(const float4*)&B[(size_t)(k0 + b_k + 8) * TT + n0 + b_n4];
        __syncthreads();
        #pragma unroll
        for (int kk = 0; kk < 16; kk++) {
            float a[8], b[8];
            *(float4*)&a[0] = *(const float4*)&As[kk][ty * 8];
            *(float4*)&a[4] = *(const float4*)&As[kk][ty * 8 + 4];
            *(float4*)&b[0] = *(const float4*)&Bs[kk][tx * 8];
            *(float4*)&b[4] = *(const float4*)&Bs[kk][tx * 8 + 4];
            #pragma unroll
            for (int i = 0; i < 8; i++)
                #pragma unroll
                for (int j = 0; j < 8; j++)
                    acc[i][j] = fmaf(a[i], b[j], acc[i][j]);
        }
        __syncthreads();
    }
    #pragma unroll
    for (int i = 0; i < 8; i++) {
        const int m = m0 + ty * 8 + i;
        #pragma unroll
        for (int j = 0; j < 8; j++)
            atomicAdd(&C[(size_t)m * TT + n0 + tx * 8 + j], acc[i][j]);
    }
}

// kw rows: add bias, L2-normalize, write fp16
__global__ void kw_norm_pack(const float* __restrict__ bias)
{
    const int w    = (blockIdx.x * blockDim.x + threadIdx.x) >> 5;
    const int lane = threadIdx.x & 31;
    if (w >= BN) return;
    const float4* row = (const float4*)(g_kw + (size_t)w * TT);
    const float4* b4  = (const float4*)bias;
    float4 v[4];
    float ss = 0.f;
    #pragma unroll
    for (int q = 0; q < 4; q++) {
        v[q] = row[lane + 32 * q];
        const float4 bb = b4[lane + 32 * q];
        v[q].x += bb.x; v[q].y += bb.y; v[q].z += bb.z; v[q].w += bb.w;
        ss += v[q].x * v[q].x + v[q].y * v[q].y + v[q].z * v[q].z + v[q].w * v[q].w;
    }
    #pragma unroll
    for (int o = 16; o > 0; o >>= 1) ss += __shfl_xor_sync(0xffffffffu, ss, o);
    const float inv = 1.f / fmaxf(sqrtf(ss), 1e-8f);
    #pragma unroll
    for (int q = 0; q < 4; q++) {
        const int e0 = (lane + 32 * q) * 4;
        *(uint32_t*)&g_kwH[(size_t)w * TT + e0] =
            pack2h(__float2half_rn(v[q].x * inv), __float2half_rn(v[q].y * inv));
        *(uint32_t*)&g_kwH[(size_t)w * TT + e0 + 2] =
            pack2h(__float2half_rn(v[q].z * inv), __float2half_rn(v[q].w * inv));
    }
}

// fused emb prep: one warp per vocab row; read fp32 once,
// write normalized fp16 (embH) + raw fp16 (embR), coalesced 8B stores.
__global__ void emb_prep(const float* __restrict__ emb)
{
    const int w    = (blockIdx.x * blockDim.x + threadIdx.x) >> 5;
    const int lane = threadIdx.x & 31;
    if (w >= VV) return;
    const float4* row = (const float4*)(emb + (size_t)w * TT);
    float4 v[4];
    float ss = 0.f;
    #pragma unroll
    for (int q = 0; q < 4; q++) {
        v[q] = row[lane + 32 * q];
        ss += v[q].x * v[q].x + v[q].y * v[q].y + v[q].z * v[q].z + v[q].w * v[q].w;
    }
    #pragma unroll
    for (int o = 16; o > 0; o >>= 1) ss += __shfl_xor_sync(0xffffffffu, ss, o);
    const float inv = 1.f / fmaxf(sqrtf(ss), 1e-8f);
    #pragma unroll
    for (int q = 0; q < 4; q++) {
        const int e0 = (lane + 32 * q) * 4;
        *(uint32_t*)&g_embR[(size_t)w * TT + e0] =
            pack2h(__float2half_rn(v[q].x), __float2half_rn(v[q].y));
        *(uint32_t*)&g_embR[(size_t)w * TT + e0 + 2] =
            pack2h(__float2half_rn(v[q].z), __float2half_rn(v[q].w));
        *(uint32_t*)&g_embH[(size_t)w * TT + e0] =
            pack2h(__float2half_rn(v[q].x * inv), __float2half_rn(v[q].y * inv));
        *(uint32_t*)&g_embH[(size_t)w * TT + e0 + 2] =
            pack2h(__float2half_rn(v[q].z * inv), __float2half_rn(v[q].w * inv));
    }
}

// =============================================================================
extern "C" void kernel_launch(void* const* d_in, const int* in_sizes, int n_in,
                              void* d_out, int out_size)
{
    const float* audio = (const float*)d_in[0];
    const float* W     = (const float*)d_in[1];
    const float* bias  = (const float*)d_in[2];
    const float* emb   = (const float*)d_in[3];
    float* out = (float*)d_out;

    cudaFuncSetAttribute(mma_gemm<0>, cudaFuncAttributeMaxDynamicSharedMemorySize, SMEMSZ);
    cudaFuncSetAttribute(mma_gemm<1>, cudaFuncAttributeMaxDynamicSharedMemorySize, SMEMSZ);

    float *kw, *rowsum;
    cudaGetSymbolAddress((void**)&kw,     g_kw);
    cudaGetSymbolAddress((void**)&rowsum, g_rowsum);

    cudaMemsetAsync(kw,     0, (size_t)BN * TT * sizeof(float), 0);
    cudaMemsetAsync(rowsum, 0, BN * sizeof(float), 0);
    cudaMemsetAsync(out,    0, (size_t)out_size * sizeof(float), 0);

    proj_gemm<<<dim3(TT / 128, BN / 128, 4), 256>>>(audio, W, kw);
    kw_norm_pack<<<BN / 8, 256>>>(bias);
    emb_prep<<<VV / 8, 256>>>(emb);

    // GEMM1: logits + exp epilogue. x = m-tiles (8, fastest -> B-tile L2 reuse)
    mma_gemm<0><<<dim3(BN / 128, VV / 128), 256, SMEMSZ>>>(nullptr);
    // GEMM2: x = n-tiles (4), y = m-tiles (8), z = split-K (9) -> 288 CTAs ~ 1 wave
    mma_gemm<1><<<dim3(TT / 128, BN / 128, 9), 256, SMEMSZ>>>(out);
}

// round 6
// speedup vs baseline: 5.9260x; 1.0385x over previous
#include <cuda_runtime.h>
#include <cuda_fp16.h>
#include <cstdint>
#include <cstddef>

#define BN 1024
#define DD 768
#define TT 512
#define VV 49408

// ------------------------- static device workspace --------------------------
__device__ float g_kw[BN * TT];            // projected keywords fp32 (split-K accum)
__device__ float g_rowsum[BN];             // softmax denominators (scaled)
__device__ __half g_kwH[BN * TT];                  // normalized kw, fp16
__device__ __half g_embH[(size_t)VV * TT];         // NORMALIZED emb [v][t], fp16
__device__ __half g_embR[(size_t)VV * TT];         // RAW emb [v][t], fp16
__device__ __half g_probs[(size_t)BN * VV];        // scaled unnormalized probs, fp16

// ------------------------------ helpers -------------------------------------
__device__ __forceinline__ uint32_t smem_u32(const void* p) {
    uint32_t a;
    asm("{ .reg .u64 t; cvta.to.shared.u64 t, %1; cvt.u32.u64 %0, t; }"
        : "=r"(a) : "l"(p));
    return a;
}
__device__ __forceinline__ void cp16(uint32_t s, const void* g) {
    asm volatile("cp.async.cg.shared.global [%0], [%1], 16;" :: "r"(s), "l"(g));
}
__device__ __forceinline__ void ldsm4(uint32_t* r, uint32_t addr) {
    asm volatile("ldmatrix.sync.aligned.m8n8.x4.shared.b16 {%0,%1,%2,%3}, [%4];"
        : "=r"(r[0]), "=r"(r[1]), "=r"(r[2]), "=r"(r[3]) : "r"(addr));
}
__device__ __forceinline__ void ldsm4t(uint32_t* r, uint32_t addr) {
    asm volatile("ldmatrix.sync.aligned.m8n8.x4.trans.shared.b16 {%0,%1,%2,%3}, [%4];"
        : "=r"(r[0]), "=r"(r[1]), "=r"(r[2]), "=r"(r[3]) : "r"(addr));
}
__device__ __forceinline__ void mma16816(float* c, const uint32_t* a, const uint32_t* b) {
    asm volatile("mma.sync.aligned.m16n8k16.row.col.f32.f16.f16.f32 "
        "{%0,%1,%2,%3}, {%4,%5,%6,%7}, {%8,%9}, {%0,%1,%2,%3};"
        : "+f"(c[0]), "+f"(c[1]), "+f"(c[2]), "+f"(c[3])
        : "r"(a[0]), "r"(a[1]), "r"(a[2]), "r"(a[3]), "r"(b[0]), "r"(b[1]));
}
__device__ __forceinline__ uint32_t pack2h(__half a, __half b) {
    return (uint32_t)__half_as_ushort(a) | ((uint32_t)__half_as_ushort(b) << 16);
}

// smem: A plane 128x144B; B plane: EPI0 128x144B, EPI1 64x272B (both <= 18432)
#define ROWA   144
#define ROWBT  272
#define PLANE  18432
#define STAGE  (2 * PLANE)       // 36864
#define NSTAGE 3
#define SMEMSZ (NSTAGE * STAGE)  // 110592 -> 2 CTAs/SM (221KB of 228KB)

// =============================================================================
// fp16 warp-MMA GEMM, CTA tile 128x128, BK=64, 256 thr, warp tile 64x32.
// 3-stage cp.async ring + fragment double-buffer software pipeline.
// EPI==0: logits -> exp epilogue -> scaled fp16 probs + rowsum atomics
// EPI==1: VQ GEMM split-K (B via ldmatrix.trans on K-major emb) -> atomicAdd out
// =============================================================================
template<int EPI>
__global__ __launch_bounds__(256, 2) void mma_gemm(float* __restrict__ outf)
{
    constexpr uint32_t LDA = (EPI == 0) ? TT : VV;   // A stride (elements)
    extern __shared__ char smem[];
    const uint32_t sbase = smem_u32(smem);
    const int tid = threadIdx.x;
    const int lane = tid & 31, wid = tid >> 5;
    const int warpM = wid & 1, warpN = wid >> 1;

    const __half *A, *B;
    int m0, n0, c0, c1;
    if (EPI == 0) {
        A = g_kwH; B = g_embH;
        m0 = blockIdx.x * 128; n0 = blockIdx.y * 128;
        c0 = 0; c1 = TT / 64;
    } else {
        A = g_probs; B = g_embR;
        n0 = blockIdx.x * 128; m0 = blockIdx.y * 128;
        const long tot = VV / 64;
        c0 = (int)((tot * blockIdx.z) / gridDim.z);
        c1 = (int)((tot * (blockIdx.z + 1)) / gridDim.z);
    }
    const int nch = c1 - c0;

    // ---- loader thread geometry (32-bit offsets, constexpr strides) ----
    const uint32_t ch   = tid & 7;           // 16B chunk within 64-elem row piece
    const uint32_t rowA = tid >> 3;          // 0..31, rows p*32 apart
    uint32_t aOff = (uint32_t)(m0 + rowA) * LDA + (uint32_t)c0 * 64 + ch * 8;
    const uint32_t aSo = rowA * ROWA + ch * 16;
    uint32_t bOff, bSo;
    if (EPI == 0) {
        bOff = (uint32_t)(n0 + rowA) * TT + (uint32_t)c0 * 64 + ch * 8;
        bSo  = aSo;
    } else {
        const uint32_t rb = tid >> 4, cb = tid & 15;   // 64 rows x 256B
        bOff = ((uint32_t)c0 * 64 + rb) * TT + (uint32_t)n0 + cb * 8;
        bSo  = rb * ROWBT + cb * 16;
    }

    auto issue = [&](uint32_t st) {
        #pragma unroll
        for (int p = 0; p < 4; p++) {
            cp16(st + aSo + p * (32 * ROWA), A + aOff + p * (32 * LDA));
            if (EPI == 0)
                cp16(st + PLANE + bSo + p * (32 * ROWA), B + bOff + p * (32 * TT));
            else
                cp16(st + PLANE + bSo + p * (16 * ROWBT), B + bOff + p * (16 * TT));
        }
        aOff += 64;
        bOff += (EPI == 0) ? 64 : 64 * TT;
    };

    // ---- compute fragment smem bases ----
    const uint32_t saOff = (uint32_t)(warpM * 64 + (lane & 15)) * ROWA + ((lane >> 4) << 4);
    uint32_t sbOff;
    if (EPI == 0)
        sbOff = PLANE + (uint32_t)(warpN * 32 + (lane & 15)) * ROWA + ((lane >> 4) << 4);
    else
        sbOff = PLANE + (uint32_t)((lane & 7) + ((lane >> 4) << 3)) * ROWBT
              + (uint32_t)(warpN * 32 + ((lane >> 3) & 1) * 8) * 2;

    float acc[4][4][4];
    #pragma unroll
    for (int i = 0; i < 4; i++)
        #pragma unroll
        for (int j = 0; j < 4; j++)
            #pragma unroll
            for (int k = 0; k < 4; k++) acc[i][j][k] = 0.f;

    // ---- prologue: 2 stages in flight ----
    issue(sbase);
    asm volatile("cp.async.commit_group;" ::: "memory");
    issue(sbase + STAGE);
    asm volatile("cp.async.commit_group;" ::: "memory");

    uint32_t a[2][4][4], b[2][2][4];
    int buf = 0;   // stage ring index of chunk c

    for (int c = 0; c < nch; c++) {
        asm volatile("cp.async.wait_group 1;" ::: "memory");
        __syncthreads();
        const uint32_t st = sbase + (uint32_t)buf * STAGE;
        // overlap next-stage issue with compute (3-stage ring)
        int nbuf = buf + 2; if (nbuf >= NSTAGE) nbuf -= NSTAGE;
        if (c + 2 < nch) issue(sbase + (uint32_t)nbuf * STAGE);
        asm volatile("cp.async.commit_group;" ::: "memory");

        // ---- ks fragment pipeline: prefetch ks+1 before mma of ks ----
        {
            #pragma unroll
            for (int mf = 0; mf < 4; mf++)
                ldsm4(a[0][mf], st + saOff + mf * (16 * ROWA));
            if (EPI == 0) {
                #pragma unroll
                for (int g = 0; g < 2; g++)
                    ldsm4(b[0][g], st + sbOff + g * (16 * ROWA));
            } else {
                #pragma unroll
                for (int g = 0; g < 2; g++)
                    ldsm4t(b[0][g], st + sbOff + g * 32);
            }
        }
        #pragma unroll
        for (int ks = 0; ks < 4; ks++) {
            const int cur = ks & 1, nxt = cur ^ 1;
            if (ks < 3) {
                const uint32_t ko = (ks + 1) * 32;
                #pragma unroll
                for (int mf = 0; mf < 4; mf++)
                    ldsm4(a[nxt][mf], st + saOff + mf * (16 * ROWA) + ko);
                if (EPI == 0) {
                    #pragma unroll
                    for (int g = 0; g < 2; g++)
                        ldsm4(b[nxt][g], st + sbOff + g * (16 * ROWA) + ko);
                } else {
                    #pragma unroll
                    for (int g = 0; g < 2; g++)
                        ldsm4t(b[nxt][g], st + sbOff + (ks + 1) * (16 * ROWBT) + g * 32);
                }
            }
            #pragma unroll
            for (int mf = 0; mf < 4; mf++)
                #pragma unroll
                for (int nf = 0; nf < 4; nf++) {
                    uint32_t bf[2] = { b[cur][nf >> 1][nf & 1],
                                       b[cur][nf >> 1][2 + (nf & 1)] };
                    mma16816(acc[mf][nf], a[cur][mf], bf);
                }
        }
        if (++buf >= NSTAGE) buf = 0;
    }

    if (EPI == 0) {
        #pragma unroll
        for (int mf = 0; mf < 4; mf++) {
            const int r0 = m0 + warpM * 64 + mf * 16 + (lane >> 2);
            float rs0 = 0.f, rs1 = 0.f;
            #pragma unroll
            for (int nf = 0; nf < 4; nf++) {
                const int cb = n0 + warpN * 32 + nf * 8 + (lane & 3) * 2;
                // p = exp(10*cos - 10) * 4096  (scale cancels in normalization)
                const float e0 = __expf(acc[mf][nf][0] * 10.f - 10.f) * 4096.f;
                const float e1 = __expf(acc[mf][nf][1] * 10.f - 10.f) * 4096.f;
                const float e2 = __expf(acc[mf][nf][2] * 10.f - 10.f) * 4096.f;
                const float e3 = __expf(acc[mf][nf][3] * 10.f - 10.f) * 4096.f;
                rs0 += e0 + e1;  rs1 += e2 + e3;
                *(uint32_t*)&g_probs[(size_t)r0 * VV + cb] =
                    pack2h(__float2half_rn(e0), __float2half_rn(e1));
                *(uint32_t*)&g_probs[(size_t)(r0 + 8) * VV + cb] =
                    pack2h(__float2half_rn(e2), __float2half_rn(e3));
            }
            rs0 += __shfl_xor_sync(0xffffffffu, rs0, 1);
            rs0 += __shfl_xor_sync(0xffffffffu, rs0, 2);
            rs1 += __shfl_xor_sync(0xffffffffu, rs1, 1);
            rs1 += __shfl_xor_sync(0xffffffffu, rs1, 2);
            if ((lane & 3) == 0) {
                atomicAdd(&g_rowsum[r0],     rs0);
                atomicAdd(&g_rowsum[r0 + 8], rs1);
            }
        }
    } else {
        #pragma unroll
        for (int mf = 0; mf < 4; mf++) {
            const int r0 = m0 + warpM * 64 + mf * 16 + (lane >> 2);
            const float s0 = 1.f / g_rowsum[r0];
            const float s1 = 1.f / g_rowsum[r0 + 8];
            #pragma unroll
            for (int nf = 0; nf < 4; nf++) {
                const int cb = n0 + warpN * 32 + nf * 8 + (lane & 3) * 2;
                atomicAdd(&outf[(size_t)r0 * TT + cb],           acc[mf][nf][0] * s0);
                atomicAdd(&outf[(size_t)r0 * TT + cb + 1],       acc[mf][nf][1] * s0);
                atomicAdd(&outf[(size_t)(r0 + 8) * TT + cb],     acc[mf][nf][2] * s1);
                atomicAdd(&outf[(size_t)(r0 + 8) * TT + cb + 1], acc[mf][nf][3] * s1);
            }
        }
    }
}

// =============================================================================
// fp32 SIMT projection GEMM, split-K z=4 (128 CTAs): kw += audio @ W
// (bias is applied in kw_norm_pack)
// =============================================================================
__global__ __launch_bounds__(256, 2)
void proj_gemm(const float* __restrict__ A, const float* __restrict__ B,
               float* __restrict__ C)
{
    __shared__ float As[16][132];
    __shared__ float Bs[16][132];
    const int tid = threadIdx.x;
    const int m0 = blockIdx.y * 128, n0 = blockIdx.x * 128;
    const int kb = blockIdx.z * (DD / 4), ke = kb + DD / 4;
    const int tx = tid & 15, ty = tid >> 4;
    const int a_row = tid >> 2, a_c4 = (tid & 3) * 4;
    const int b_k = tid >> 5, b_n4 = (tid & 31) * 4;

    float acc[8][8];
    #pragma unroll
    for (int i = 0; i < 8; i++)
        #pragma unroll
        for (int j = 0; j < 8; j++) acc[i][j] = 0.f;

    for (int k0 = kb; k0 < ke; k0 += 16) {
        float4 va0 = *(const float4*)&A[(size_t)(m0 + a_row)      * DD + k0 + a_c4];
        float4 va1 = *(const float4*)&A[(size_t)(m0 + a_row + 64) * DD + k0 + a_c4];
        As[a_c4 + 0][a_row] = va0.x;  As[a_c4 + 1][a_row] = va0.y;
        As[a_c4 + 2][a_row] = va0.z;  As[a_c4 + 3][a_row] = va0.w;
        As[a_c4 + 0][a_row + 64] = va1.x;  As[a_c4 + 1][a_row + 64] = va1.y;
        As[a_c4 + 2][a_row + 64] = va1.z;  As[a_c4 + 3][a_row + 64] = va1.w;
        *(float4*)&Bs[b_k][b_n4]     = *(const float4*)&B[(size_t)(k0 + b_k)     * TT + n0 + b_n4];
        *(float4*)&Bs[b_k + 8][b_n4] = *(const float4*)&B[(size_t)(k0 + b_k + 8) * TT + n0 + b_n4];
        __syncthreads();
        #pragma unroll
        for (int kk = 0; kk < 16; kk++) {
            float a[8], b[8];
            *(float4*)&a[0] = *(const float4*)&As[kk][ty * 8];
            *(float4*)&a[4] = *(const float4*)&As[kk][ty * 8 + 4];
            *(float4*)&b[0] = *(const float4*)&Bs[kk][tx * 8];
            *(float4*)&b[4] = *(const float4*)&Bs[kk][tx * 8 + 4];
            #pragma unroll
            for (int i = 0; i < 8; i++)
                #pragma unroll
                for (int j = 0; j < 8; j++)
                    acc[i][j] = fmaf(a[i], b[j], acc[i][j]);
        }
        __syncthreads();
    }
    #pragma unroll
    for (int i = 0; i < 8; i++) {
        const int m = m0 + ty * 8 + i;
        #pragma unroll
        for (int j = 0; j < 8; j++)
            atomicAdd(&C[(size_t)m * TT + n0 + tx * 8 + j], acc[i][j]);
    }
}

// kw rows: add bias, L2-normalize, write fp16
__global__ void kw_norm_pack(const float* __restrict__ bias)
{
    const int w    = (blockIdx.x * blockDim.x + threadIdx.x) >> 5;
    const int lane = threadIdx.x & 31;
    if (w >= BN) return;
    const float4* row = (const float4*)(g_kw + (size_t)w * TT);
    const float4* b4  = (const float4*)bias;
    float4 v[4];
    float ss = 0.f;
    #pragma unroll
    for (int q = 0; q < 4; q++) {
        v[q] = row[lane + 32 * q];
        const float4 bb = b4[lane + 32 * q];
        v[q].x += bb.x; v[q].y += bb.y; v[q].z += bb.z; v[q].w += bb.w;
        ss += v[q].x * v[q].x + v[q].y * v[q].y + v[q].z * v[q].z + v[q].w * v[q].w;
    }
    #pragma unroll
    for (int o = 16; o > 0; o >>= 1) ss += __shfl_xor_sync(0xffffffffu, ss, o);
    const float inv = 1.f / fmaxf(sqrtf(ss), 1e-8f);
    #pragma unroll
    for (int q = 0; q < 4; q++) {
        const int e0 = (lane + 32 * q) * 4;
        *(uint32_t*)&g_kwH[(size_t)w * TT + e0] =
            pack2h(__float2half_rn(v[q].x * inv), __float2half_rn(v[q].y * inv));
        *(uint32_t*)&g_kwH[(size_t)w * TT + e0 + 2] =
            pack2h(__float2half_rn(v[q].z * inv), __float2half_rn(v[q].w * inv));
    }
}

// fused emb prep: one warp per vocab row; read fp32 once,
// write normalized fp16 (embH) + raw fp16 (embR), coalesced 8B stores.
__global__ void emb_prep(const float* __restrict__ emb)
{
    const int w    = (blockIdx.x * blockDim.x + threadIdx.x) >> 5;
    const int lane = threadIdx.x & 31;
    if (w >= VV) return;
    const float4* row = (const float4*)(emb + (size_t)w * TT);
    float4 v[4];
    float ss = 0.f;
    #pragma unroll
    for (int q = 0; q < 4; q++) {
        v[q] = row[lane + 32 * q];
        ss += v[q].x * v[q].x + v[q].y * v[q].y + v[q].z * v[q].z + v[q].w * v[q].w;
    }
    #pragma unroll
    for (int o = 16; o > 0; o >>= 1) ss += __shfl_xor_sync(0xffffffffu, ss, o);
    const float inv = 1.f / fmaxf(sqrtf(ss), 1e-8f);
    #pragma unroll
    for (int q = 0; q < 4; q++) {
        const int e0 = (lane + 32 * q) * 4;
        *(uint32_t*)&g_embR[(size_t)w * TT + e0] =
            pack2h(__float2half_rn(v[q].x), __float2half_rn(v[q].y));
        *(uint32_t*)&g_embR[(size_t)w * TT + e0 + 2] =
            pack2h(__float2half_rn(v[q].z), __float2half_rn(v[q].w));
        *(uint32_t*)&g_embH[(size_t)w * TT + e0] =
            pack2h(__float2half_rn(v[q].x * inv), __float2half_rn(v[q].y * inv));
        *(uint32_t*)&g_embH[(size_t)w * TT + e0 + 2] =
            pack2h(__float2half_rn(v[q].z * inv), __float2half_rn(v[q].w * inv));
    }
}

// =============================================================================
extern "C" void kernel_launch(void* const* d_in, const int* in_sizes, int n_in,
                              void* d_out, int out_size)
{
    const float* audio = (const float*)d_in[0];
    const float* W     = (const float*)d_in[1];
    const float* bias  = (const float*)d_in[2];
    const float* emb   = (const float*)d_in[3];
    float* out = (float*)d_out;

    cudaFuncSetAttribute(mma_gemm<0>, cudaFuncAttributeMaxDynamicSharedMemorySize, SMEMSZ);
    cudaFuncSetAttribute(mma_gemm<1>, cudaFuncAttributeMaxDynamicSharedMemorySize, SMEMSZ);

    float *kw, *rowsum;
    cudaGetSymbolAddress((void**)&kw,     g_kw);
    cudaGetSymbolAddress((void**)&rowsum, g_rowsum);

    cudaMemsetAsync(kw,     0, (size_t)BN * TT * sizeof(float), 0);
    cudaMemsetAsync(rowsum, 0, BN * sizeof(float), 0);
    cudaMemsetAsync(out,    0, (size_t)out_size * sizeof(float), 0);

    proj_gemm<<<dim3(TT / 128, BN / 128, 4), 256>>>(audio, W, kw);
    kw_norm_pack<<<BN / 8, 256>>>(bias);
    emb_prep<<<VV / 8, 256>>>(emb);

    // GEMM1: logits + exp epilogue. x = m-tiles (8, fastest -> B-tile L2 reuse)
    mma_gemm<0><<<dim3(BN / 128, VV / 128), 256, SMEMSZ>>>(nullptr);
    // GEMM2: x = n-tiles (4), y = m-tiles (8), z = split-K (9) -> 288 CTAs ~ 1 wave
    mma_gemm<1><<<dim3(TT / 128, BN / 128, 9), 256, SMEMSZ>>>(out);
}